// round 7
// baseline (speedup 1.0000x reference)
#include <cuda_runtime.h>

// ---------------- problem constants ----------------
#define IMG_H 360
#define IMG_W 640
#define N_PTS (IMG_H * IMG_W)      // 230400
#define N_PLANES 1000
#define MIN_PTS 5000

#define CXc 334.081f
#define CYc 169.808f
#define FXc 460.585f
#define FYc 460.268f

#define F_INF __int_as_float(0x7f800000)
#define NEG_FLT_MAX (-3.402823466e38f)
#define POS_FLT_MAX ( 3.402823466e38f)

// ---------------- device scratch (no allocs; self-cleaning per call) ----------------
static __device__ double g_sX = 0.0, g_sY = 0.0, g_sZ = 0.0, g_sL = 0.0;
static __device__ int    g_cnt = 0;
static __device__ float  g_max = NEG_FLT_MAX;
static __device__ float4 g_pts[N_PTS];         // UNNORMALIZED nan_cloud
static __device__ float4 g_plane[N_PLANES];    // (n0,n1,n2,kk) from normalized pts
static __device__ int    g_counts[N_PLANES];   // zero-init, reset by k_best
static __device__ int    g_icnt = 0;
static __device__ float  g_zmax = NEG_FLT_MAX, g_zmin = POS_FLT_MAX;
static __device__ double g_sZC = 0.0;          // sum of inlier zc
static __device__ float  g_bp[8];              // a,b,c,d, r20,r21,r22, d/c

// ---------------- f32x2 packed math (Blackwell FFMA2) ----------------
__device__ __forceinline__ unsigned long long pack2(float a, float b) {
    unsigned long long r;
    asm("mov.b64 %0, {%1, %2};" : "=l"(r) : "f"(a), "f"(b));
    return r;
}
__device__ __forceinline__ unsigned long long fma2(unsigned long long a,
                                                   unsigned long long b,
                                                   unsigned long long c) {
    unsigned long long d;
    asm("fma.rn.f32x2 %0, %1, %2, %3;" : "=l"(d) : "l"(a), "l"(b), "l"(c));
    return d;
}
__device__ __forceinline__ void unpack2(unsigned long long v, float& lo, float& hi) {
    asm("mov.b64 {%0, %1}, %2;" : "=f"(lo), "=f"(hi) : "l"(v));
}

// ---------------- helpers ----------------
__device__ __forceinline__ unsigned rotl32(unsigned v, int d) {
    return (v << d) | (v >> (32 - d));
}

// JAX threefry2x32, 20 rounds
__device__ __forceinline__ void threefry2x32(unsigned k0, unsigned k1,
                                             unsigned x0, unsigned x1,
                                             unsigned& o0, unsigned& o1) {
    unsigned ks2 = k0 ^ k1 ^ 0x1BD11BDAu;
#define TF_R(r) { x0 += x1; x1 = rotl32(x1, (r)); x1 ^= x0; }
    x0 += k0;  x1 += k1;
    TF_R(13) TF_R(15) TF_R(26) TF_R(6)
    x0 += k1;  x1 += ks2 + 1u;
    TF_R(17) TF_R(29) TF_R(16) TF_R(24)
    x0 += ks2; x1 += k0 + 2u;
    TF_R(13) TF_R(15) TF_R(26) TF_R(6)
    x0 += k0;  x1 += k1 + 3u;
    TF_R(17) TF_R(29) TF_R(16) TF_R(24)
    x0 += k1;  x1 += ks2 + 4u;
    TF_R(13) TF_R(15) TF_R(26) TF_R(6)
    x0 += ks2; x1 += k0 + 5u;
#undef TF_R
    o0 = x0; o1 = x1;
}

__device__ __forceinline__ float get_thresh(int epoch) {
    float a = (float)(0.025 - 0.001 * (double)epoch);
    return fmaxf(a, 0.005f);
}

__device__ __forceinline__ void atomicMaxF(float* addr, float v) {
    if (!(v == v)) return;
    int old = __float_as_int(*addr);
    while (__int_as_float(old) < v) {
        int assumed = old;
        old = atomicCAS((int*)addr, assumed, __float_as_int(v));
        if (old == assumed) break;
    }
}
__device__ __forceinline__ void atomicMinF(float* addr, float v) {
    if (!(v == v)) return;
    int old = __float_as_int(*addr);
    while (__int_as_float(old) > v) {
        int assumed = old;
        old = atomicCAS((int*)addr, assumed, __float_as_int(v));
        if (old == assumed) break;
    }
}

// ---------------- kernels ----------------

// Stage A: point clouds, masked loss sums, nan_cloud + global max.
// One combined reduction stage: interleaved warp shuffles, 1 syncthreads.
__global__ void k_pcd(const float* __restrict__ fake, const float* __restrict__ real) {
    int i = blockIdx.x * blockDim.x + threadIdx.x;  // exactly N_PTS threads
    int lane = threadIdx.x & 31, w = threadIdx.x >> 5;
    int r = i / IMG_W, c = i % IMG_W;
    float dr = real[i], df = fake[i];
    bool vr = (dr > 0.f) && (dr < 65535.f);
    bool vf = (df > 0.f) && (df < 65535.f);
    float cf = (float)c, rf = (float)r;

    float zr = dr / 1000.f, zf = df / 1000.f;
    float xr = zr * (cf - CXc) / FXc, yr = zr * (rf - CYc) / FYc;
    float xf = zf * (cf - CXc) / FXc, yf = zf * (rf - CYc) / FYc;
    xr *= 1000.f; yr *= 1000.f; zr *= 1000.f;
    xf *= 1000.f; yf *= 1000.f; zf *= 1000.f;
    if (xr == 0.f) xr = 1e-7f;  if (yr == 0.f) yr = 1e-7f;  if (zr == 0.f) zr = 1e-7f;
    if (xf == 0.f) xf = 1e-7f;  if (yf == 0.f) yf = 1e-7f;  if (zf == 0.f) zf = 1e-7f;

    double dx = 0.0, dy = 0.0, dz = 0.0, dl = 0.0;
    int mm = 0;
    if (vr && vf) {
        float ex = xr - xf, ey = yr - yf, ez = zr - zf;
        dx = (double)(ex * ex); dy = (double)(ey * ey); dz = (double)(ez * ez);
        float d0 = logf(fabsf(zr)) - logf(fabsf(zf));
        dl = (double)(d0 * d0);
        mm = 1;
    }
    float4 nc = vf ? make_float4(xf, yf, zf, 0.f) : make_float4(0.f, 0.f, 0.f, 0.f);
    g_pts[i] = nc;
    float mxv = fmaxf(nc.x, fmaxf(nc.y, nc.z));

    // interleaved warp reductions (good ILP)
#pragma unroll
    for (int o = 16; o; o >>= 1) {
        dx += __shfl_down_sync(0xffffffffu, dx, o);
        dy += __shfl_down_sync(0xffffffffu, dy, o);
        dz += __shfl_down_sync(0xffffffffu, dz, o);
        dl += __shfl_down_sync(0xffffffffu, dl, o);
        mm += __shfl_down_sync(0xffffffffu, mm, o);
        mxv = fmaxf(mxv, __shfl_down_sync(0xffffffffu, mxv, o));
    }
    __shared__ double sdx[8], sdy[8], sdz[8], sdl[8];
    __shared__ int   smm[8];
    __shared__ float smx[8];
    if (lane == 0) { sdx[w] = dx; sdy[w] = dy; sdz[w] = dz; sdl[w] = dl; smm[w] = mm; smx[w] = mxv; }
    __syncthreads();
    if (w == 0) {
        dx  = (lane < 8) ? sdx[lane] : 0.0;
        dy  = (lane < 8) ? sdy[lane] : 0.0;
        dz  = (lane < 8) ? sdz[lane] : 0.0;
        dl  = (lane < 8) ? sdl[lane] : 0.0;
        mm  = (lane < 8) ? smm[lane] : 0;
        mxv = (lane < 8) ? smx[lane] : -F_INF;
#pragma unroll
        for (int o = 4; o; o >>= 1) {
            dx += __shfl_down_sync(0xffffffffu, dx, o);
            dy += __shfl_down_sync(0xffffffffu, dy, o);
            dz += __shfl_down_sync(0xffffffffu, dz, o);
            dl += __shfl_down_sync(0xffffffffu, dl, o);
            mm += __shfl_down_sync(0xffffffffu, mm, o);
            mxv = fmaxf(mxv, __shfl_down_sync(0xffffffffu, mxv, o));
        }
        if (lane == 0) {
            atomicAdd(&g_sX, dx);
            atomicAdd(&g_sY, dy);
            atomicAdd(&g_sZ, dz);
            atomicAdd(&g_sL, dl);
            atomicAdd(&g_cnt, mm);
            atomicMaxF(&g_max, mxv);
        }
    }
}

// Stage B: 1000 RANSAC planes, JAX-exact threefry randint, prefetched point loads
__global__ void k_planes() {
    int j = blockIdx.x * blockDim.x + threadIdx.x;
    if (j >= N_PLANES) return;
    float m = g_max;

    unsigned idxs[3];
#pragma unroll
    for (int k = 0; k < 3; k++) {
        unsigned f = (unsigned)(j * 3 + k);
        unsigned o0, o1;
        threefry2x32(0u, 42u, f, 3000u + f, o0, o1);
        // span = 230400 > 2^16 => JAX multiplier wraps to 0 => idx = lower_bits % span
        idxs[k] = o1 % (unsigned)N_PTS;
    }
    float4 q0 = g_pts[idxs[0]];
    float4 q1 = g_pts[idxs[1]];
    float4 q2 = g_pts[idxs[2]];
    float3 p0 = make_float3(q0.x / m, q0.y / m, q0.z / m);
    float3 p1 = make_float3(q1.x / m, q1.y / m, q1.z / m);
    float3 p2 = make_float3(q2.x / m, q2.y / m, q2.z / m);

    float ax = p1.x - p0.x, ay = p1.y - p0.y, az = p1.z - p0.z;
    float bx = p2.x - p0.x, by = p2.y - p0.y, bz = p2.z - p0.z;
    float nx = ay * bz - az * by;
    float ny = az * bx - ax * bz;
    float nz = ax * by - ay * bx;
    float nn = sqrtf(nx * nx + ny * ny + nz * nz);
    nx /= nn; ny /= nn; nz /= nn;
    float kk = -(nx * p1.x + ny * p1.y + nz * p1.z);
    g_plane[j] = make_float4(nx, ny, nz, kk);
}

// Stage C: inlier counts. 256-pt tile (128 packed pairs), 4 planes/thread,
// FFMA2 packed math. No fences, no tail — argmax moved to k_best.
#define CT 256
#define CP (CT / 2)               // 128 pairs
#define CB (N_PTS / CT)           // 900, exact
__global__ void __launch_bounds__(256, 5) k_counts(const int* __restrict__ ep) {
    __shared__ ulonglong2 sxy[CP];           // (x2, y2) -> one LDS.128
    __shared__ unsigned long long szz[CP];   // z2       -> LDS.64

    float th = get_thresh(*ep);
    float m = g_max;
    int t = threadIdx.x;

    // planes (broadcast into both packed halves)
    unsigned long long A[4], B4[4], C4[4], K4[4];
    int cnt[4] = {0, 0, 0, 0};
#pragma unroll
    for (int p = 0; p < 4; p++) {
        int j = t + p * 256;
        float4 pl = g_plane[j < N_PLANES ? j : 0];
        A[p]  = pack2(pl.x, pl.x);
        B4[p] = pack2(pl.y, pl.y);
        C4[p] = pack2(pl.z, pl.z);
        K4[p] = pack2(pl.w, pl.w);
    }

    // tile load: point pairs, normalized exactly like reference (f32 divide)
    int base = blockIdx.x * CT;
    if (t < CP) {
        float4 q0 = g_pts[base + 2 * t];
        float4 q1 = g_pts[base + 2 * t + 1];
        sxy[t] = make_ulonglong2(pack2(q0.x / m, q1.x / m), pack2(q0.y / m, q1.y / m));
        szz[t] = pack2(q0.z / m, q1.z / m);
    }
    __syncthreads();

#pragma unroll 8
    for (int i = 0; i < CP; i++) {
        ulonglong2 xy = sxy[i];
        unsigned long long z2 = szz[i];
#pragma unroll
        for (int p = 0; p < 4; p++) {
            unsigned long long d2 = fma2(xy.x, A[p], fma2(xy.y, B4[p], fma2(z2, C4[p], K4[p])));
            float d0, d1; unpack2(d2, d0, d1);
            cnt[p] += (fabsf(d0) <= th);
            cnt[p] += (fabsf(d1) <= th);
        }
    }
#pragma unroll
    for (int p = 0; p < 4; p++) {
        int j = t + p * 256;
        if (j < N_PLANES) atomicAdd(&g_counts[j], cnt[p]);
    }
}

// Stage C2 (tiny): argmax (first max) + best-plane rotation + counts self-clean.
__global__ void k_best() {
    __shared__ int sv[256], si[256];
    int t = threadIdx.x;
    int bv = -2, bi = 0;
    for (int j = t; j < N_PLANES; j += 256) {
        int cc = g_counts[j];
        int v = (cc > MIN_PTS) ? cc : -1;
        if (v > bv) { bv = v; bi = j; }   // ascending j => first max kept
    }
    sv[t] = bv; si[t] = bi;
    __syncthreads();
    for (int s = 128; s > 0; s >>= 1) {
        if (t < s) {
            if (sv[t + s] > sv[t] || (sv[t + s] == sv[t] && si[t + s] < si[t])) {
                sv[t] = sv[t + s]; si[t] = si[t + s];
            }
        }
        __syncthreads();
    }
    if (t == 0) {
        int best = si[0];
        float4 pl = g_plane[best];
        float a = pl.x, b = pl.y, c = pl.z, d = pl.w;
        float n2 = a * a + b * b + c * c;
        float cos_t = c / sqrtf(n2);
        float sin_t = sqrtf((a * a + b * b) / n2);
        float sab = sqrtf(a * a + b * b);
        float u1 = b / sab, u2 = -a / sab;
        g_bp[0] = a; g_bp[1] = b; g_bp[2] = c; g_bp[3] = d;
        g_bp[4] = -u2 * sin_t;   // R[2,0]
        g_bp[5] =  u1 * sin_t;   // R[2,1]
        g_bp[6] =  cos_t;        // R[2,2]
        g_bp[7] =  d / c;        // trans z
    }
    __syncthreads();
    for (int j = t; j < N_PLANES; j += 256) g_counts[j] = 0;  // self-clean
}

// Stage D: single pass inlier stats. One combined reduction, no fences.
// Uses identity: sum|zc-zmax| = icnt*zmax - S, sum|zc-zmin| = S - icnt*zmin.
__global__ void k_zc(const int* __restrict__ ep) {
    float th = get_thresh(*ep);
    float m = g_max;
    int i = blockIdx.x * blockDim.x + threadIdx.x;
    int lane = threadIdx.x & 31, w = threadIdx.x >> 5;
    float4 q = g_pts[i];
    float x = q.x / m, y = q.y / m, z = q.z / m;
    float dist = fmaf(x, g_bp[0], fmaf(y, g_bp[1], fmaf(z, g_bp[2], g_bp[3])));
    bool inl = fabsf(dist) <= th;
    float zc = x * g_bp[4] + y * g_bp[5] + (z + g_bp[7]) * g_bp[6];

    int    ic  = inl ? 1 : 0;
    float  zmx = inl ? zc : -F_INF;
    float  zmn = inl ? zc :  F_INF;
    double s   = inl ? (double)zc : 0.0;

#pragma unroll
    for (int o = 16; o; o >>= 1) {
        ic += __shfl_down_sync(0xffffffffu, ic, o);
        zmx = fmaxf(zmx, __shfl_down_sync(0xffffffffu, zmx, o));
        zmn = fminf(zmn, __shfl_down_sync(0xffffffffu, zmn, o));
        s  += __shfl_down_sync(0xffffffffu, s, o);
    }
    __shared__ int   sic[8];
    __shared__ float smx2[8], smn2[8];
    __shared__ double sss[8];
    if (lane == 0) { sic[w] = ic; smx2[w] = zmx; smn2[w] = zmn; sss[w] = s; }
    __syncthreads();
    if (w == 0) {
        ic  = (lane < 8) ? sic[lane]  : 0;
        zmx = (lane < 8) ? smx2[lane] : -F_INF;
        zmn = (lane < 8) ? smn2[lane] :  F_INF;
        s   = (lane < 8) ? sss[lane]  : 0.0;
#pragma unroll
        for (int o = 4; o; o >>= 1) {
            ic += __shfl_down_sync(0xffffffffu, ic, o);
            zmx = fmaxf(zmx, __shfl_down_sync(0xffffffffu, zmx, o));
            zmn = fminf(zmn, __shfl_down_sync(0xffffffffu, zmn, o));
            s  += __shfl_down_sync(0xffffffffu, s, o);
        }
        if (lane == 0) {
            atomicAdd(&g_icnt, ic);
            atomicMaxF(&g_zmax, zmx);
            atomicMinF(&g_zmin, zmn);
            atomicAdd(&g_sZC, s);
        }
    }
}

// Stage E (tiny): finalize output + self-clean ALL accumulators.
__global__ void k_fin(float* __restrict__ out, int n) {
    if (threadIdx.x != 0) return;
    float cntf = (float)(g_cnt > 1 ? g_cnt : 1);
    float lX = sqrtf((float)g_sX / cntf);
    float lY = sqrtf((float)g_sY / cntf);
    float lZ = sqrtf((float)g_sZ / cntf);
    float rl = 10000.f * sqrtf((float)g_sL / cntf);
    float l17 = rl * fabsf(10.f * (3.f - expf(lX) - expf(lY) - expf(lZ)));

    int icr = g_icnt;
    float below, above;
    if (icr <= 0) {
        below = 0.f; above = 0.f;
    } else {
        float meanz = (float)(g_sZC / (double)icr);
        below = g_zmax - meanz;
        above = meanz - g_zmin;
    }
    if (above == 0.f) above = 1e-7f;
    float pmd = 1000.f * (above + below);
    float curv = l17 + pmd;
    float vals[7] = { rl, lX, lY, lZ, pmd, l17, curv };
    for (int k = 0; k < n; k++) out[k] = (k < 7) ? vals[k] : 0.f;

    // self-clean for next call
    g_sX = 0.0; g_sY = 0.0; g_sZ = 0.0; g_sL = 0.0;
    g_cnt = 0;  g_icnt = 0;
    g_max  = NEG_FLT_MAX;
    g_zmax = NEG_FLT_MAX;
    g_zmin = POS_FLT_MAX;
    g_sZC  = 0.0;
}

// ---------------- launch ----------------
extern "C" void kernel_launch(void* const* d_in, const int* in_sizes, int n_in,
                              void* d_out, int out_size) {
    const float* fake = (const float*)d_in[0];
    const float* real = (const float*)d_in[1];
    const int*   ep   = (const int*)d_in[2];
    float* out = (float*)d_out;

    const int NB = N_PTS / 256;  // 900, exact

    k_pcd<<<NB, 256>>>(fake, real);
    k_planes<<<8, 128>>>();
    k_counts<<<CB, 256>>>(ep);
    k_best<<<1, 256>>>();
    k_zc<<<NB, 256>>>(ep);
    k_fin<<<1, 32>>>(out, out_size);
}

// round 9
// speedup vs baseline: 1.5181x; 1.5181x over previous
#include <cuda_runtime.h>

// ---------------- problem constants ----------------
#define IMG_H 360
#define IMG_W 640
#define N_PTS (IMG_H * IMG_W)      // 230400
#define N_PLANES 1000
#define MIN_PTS 5000

#define CXc 334.081f
#define CYc 169.808f
#define FXc 460.585f
#define FYc 460.268f

#define F_INF __int_as_float(0x7f800000)
#define NEG_FLT_MAX (-3.402823466e38f)
#define POS_FLT_MAX ( 3.402823466e38f)

// ---------------- device scratch (no allocs; self-cleaning per call) ----------------
static __device__ double g_sX = 0.0, g_sY = 0.0, g_sZ = 0.0, g_sL = 0.0;
static __device__ int    g_cnt = 0;
static __device__ float  g_max = NEG_FLT_MAX;
static __device__ float4 g_pts[N_PTS];         // UNNORMALIZED nan_cloud
static __device__ float4 g_plane[N_PLANES];    // (n0,n1,n2,kk) from normalized pts
static __device__ int    g_counts[N_PLANES];   // zero-init, reset by k_best
static __device__ int    g_icnt = 0;
static __device__ float  g_zmax = NEG_FLT_MAX, g_zmin = POS_FLT_MAX;
static __device__ double g_sZC = 0.0;          // sum of inlier zc
static __device__ float  g_bp[8];              // a,b,c,d, r20,r21,r22, d/c

// ---------------- f32x2 packed math (Blackwell FFMA2) ----------------
__device__ __forceinline__ unsigned long long pack2(float a, float b) {
    unsigned long long r;
    asm("mov.b64 %0, {%1, %2};" : "=l"(r) : "f"(a), "f"(b));
    return r;
}
__device__ __forceinline__ unsigned long long fma2(unsigned long long a,
                                                   unsigned long long b,
                                                   unsigned long long c) {
    unsigned long long d;
    asm("fma.rn.f32x2 %0, %1, %2, %3;" : "=l"(d) : "l"(a), "l"(b), "l"(c));
    return d;
}
__device__ __forceinline__ void unpack2(unsigned long long v, float& lo, float& hi) {
    asm("mov.b64 {%0, %1}, %2;" : "=f"(lo), "=f"(hi) : "l"(v));
}

// ---------------- helpers ----------------
__device__ __forceinline__ unsigned rotl32(unsigned v, int d) {
    return (v << d) | (v >> (32 - d));
}

// JAX threefry2x32, 20 rounds
__device__ __forceinline__ void threefry2x32(unsigned k0, unsigned k1,
                                             unsigned x0, unsigned x1,
                                             unsigned& o0, unsigned& o1) {
    unsigned ks2 = k0 ^ k1 ^ 0x1BD11BDAu;
#define TF_R(r) { x0 += x1; x1 = rotl32(x1, (r)); x1 ^= x0; }
    x0 += k0;  x1 += k1;
    TF_R(13) TF_R(15) TF_R(26) TF_R(6)
    x0 += k1;  x1 += ks2 + 1u;
    TF_R(17) TF_R(29) TF_R(16) TF_R(24)
    x0 += ks2; x1 += k0 + 2u;
    TF_R(13) TF_R(15) TF_R(26) TF_R(6)
    x0 += k0;  x1 += k1 + 3u;
    TF_R(17) TF_R(29) TF_R(16) TF_R(24)
    x0 += k1;  x1 += ks2 + 4u;
    TF_R(13) TF_R(15) TF_R(26) TF_R(6)
    x0 += ks2; x1 += k0 + 5u;
#undef TF_R
    o0 = x0; o1 = x1;
}

__device__ __forceinline__ float get_thresh(int epoch) {
    float a = (float)(0.025 - 0.001 * (double)epoch);
    return fmaxf(a, 0.005f);
}

// block reductions for blockDim.x == 256 (8 warps)
__device__ __forceinline__ double blockSumD(double v) {
    __shared__ double sh[8];
    int lane = threadIdx.x & 31, w = threadIdx.x >> 5;
    for (int o = 16; o; o >>= 1) v += __shfl_down_sync(0xffffffffu, v, o);
    __syncthreads();
    if (lane == 0) sh[w] = v;
    __syncthreads();
    if (w == 0) {
        v = (lane < 8) ? sh[lane] : 0.0;
        for (int o = 4; o; o >>= 1) v += __shfl_down_sync(0xffffffffu, v, o);
    }
    return v;
}
__device__ __forceinline__ int blockSumI(int v) {
    __shared__ int sh[8];
    int lane = threadIdx.x & 31, w = threadIdx.x >> 5;
    for (int o = 16; o; o >>= 1) v += __shfl_down_sync(0xffffffffu, v, o);
    __syncthreads();
    if (lane == 0) sh[w] = v;
    __syncthreads();
    if (w == 0) {
        v = (lane < 8) ? sh[lane] : 0;
        for (int o = 4; o; o >>= 1) v += __shfl_down_sync(0xffffffffu, v, o);
    }
    return v;
}
__device__ __forceinline__ float blockMaxF(float v) {
    __shared__ float sh[8];
    int lane = threadIdx.x & 31, w = threadIdx.x >> 5;
    for (int o = 16; o; o >>= 1) v = fmaxf(v, __shfl_down_sync(0xffffffffu, v, o));
    __syncthreads();
    if (lane == 0) sh[w] = v;
    __syncthreads();
    if (w == 0) {
        v = (lane < 8) ? sh[lane] : -F_INF;
        for (int o = 4; o; o >>= 1) v = fmaxf(v, __shfl_down_sync(0xffffffffu, v, o));
    }
    return v;
}
__device__ __forceinline__ float blockMinF(float v) {
    __shared__ float sh[8];
    int lane = threadIdx.x & 31, w = threadIdx.x >> 5;
    for (int o = 16; o; o >>= 1) v = fminf(v, __shfl_down_sync(0xffffffffu, v, o));
    __syncthreads();
    if (lane == 0) sh[w] = v;
    __syncthreads();
    if (w == 0) {
        v = (lane < 8) ? sh[lane] : F_INF;
        for (int o = 4; o; o >>= 1) v = fminf(v, __shfl_down_sync(0xffffffffu, v, o));
    }
    return v;
}

__device__ __forceinline__ void atomicMaxF(float* addr, float v) {
    if (!(v == v)) return;
    int old = __float_as_int(*addr);
    while (__int_as_float(old) < v) {
        int assumed = old;
        old = atomicCAS((int*)addr, assumed, __float_as_int(v));
        if (old == assumed) break;
    }
}
__device__ __forceinline__ void atomicMinF(float* addr, float v) {
    if (!(v == v)) return;
    int old = __float_as_int(*addr);
    while (__int_as_float(old) > v) {
        int assumed = old;
        old = atomicCAS((int*)addr, assumed, __float_as_int(v));
        if (old == assumed) break;
    }
}

// ---------------- kernels ----------------

// Stage A: point clouds, masked loss sums, nan_cloud + global max
__global__ void k_pcd(const float* __restrict__ fake, const float* __restrict__ real) {
    int i = blockIdx.x * blockDim.x + threadIdx.x;  // exactly N_PTS threads
    int r = i / IMG_W, c = i % IMG_W;
    float dr = real[i], df = fake[i];
    bool vr = (dr > 0.f) && (dr < 65535.f);
    bool vf = (df > 0.f) && (df < 65535.f);
    float cf = (float)c, rf = (float)r;

    float zr = dr / 1000.f, zf = df / 1000.f;
    float xr = zr * (cf - CXc) / FXc, yr = zr * (rf - CYc) / FYc;
    float xf = zf * (cf - CXc) / FXc, yf = zf * (rf - CYc) / FYc;
    xr *= 1000.f; yr *= 1000.f; zr *= 1000.f;
    xf *= 1000.f; yf *= 1000.f; zf *= 1000.f;
    if (xr == 0.f) xr = 1e-7f;  if (yr == 0.f) yr = 1e-7f;  if (zr == 0.f) zr = 1e-7f;
    if (xf == 0.f) xf = 1e-7f;  if (yf == 0.f) yf = 1e-7f;  if (zf == 0.f) zf = 1e-7f;

    double dx = 0.0, dy = 0.0, dz = 0.0, dl = 0.0;
    int mm = 0;
    if (vr && vf) {
        float ex = xr - xf, ey = yr - yf, ez = zr - zf;
        dx = (double)(ex * ex); dy = (double)(ey * ey); dz = (double)(ez * ez);
        float d0 = logf(fabsf(zr)) - logf(fabsf(zf));
        dl = (double)(d0 * d0);
        mm = 1;
    }
    float4 nc = vf ? make_float4(xf, yf, zf, 0.f) : make_float4(0.f, 0.f, 0.f, 0.f);
    g_pts[i] = nc;
    float mxv = fmaxf(nc.x, fmaxf(nc.y, nc.z));

    double s;
    s = blockSumD(dx); if (threadIdx.x == 0) atomicAdd(&g_sX, s);
    s = blockSumD(dy); if (threadIdx.x == 0) atomicAdd(&g_sY, s);
    s = blockSumD(dz); if (threadIdx.x == 0) atomicAdd(&g_sZ, s);
    s = blockSumD(dl); if (threadIdx.x == 0) atomicAdd(&g_sL, s);
    int cs = blockSumI(mm); if (threadIdx.x == 0) atomicAdd(&g_cnt, cs);
    float bm = blockMaxF(mxv); if (threadIdx.x == 0) atomicMaxF(&g_max, bm);
}

// Stage B: 1000 RANSAC planes, JAX-exact threefry randint, prefetched point loads
__global__ void k_planes() {
    int j = blockIdx.x * blockDim.x + threadIdx.x;
    if (j >= N_PLANES) return;
    float m = g_max;

    unsigned idxs[3];
#pragma unroll
    for (int k = 0; k < 3; k++) {
        unsigned f = (unsigned)(j * 3 + k);
        unsigned o0, o1;
        threefry2x32(0u, 42u, f, 3000u + f, o0, o1);
        // span = 230400 > 2^16 => JAX multiplier wraps to 0 => idx = lower_bits % span
        idxs[k] = o1 % (unsigned)N_PTS;
    }
    float4 q0 = g_pts[idxs[0]];
    float4 q1 = g_pts[idxs[1]];
    float4 q2 = g_pts[idxs[2]];
    float3 p0 = make_float3(q0.x / m, q0.y / m, q0.z / m);
    float3 p1 = make_float3(q1.x / m, q1.y / m, q1.z / m);
    float3 p2 = make_float3(q2.x / m, q2.y / m, q2.z / m);

    float ax = p1.x - p0.x, ay = p1.y - p0.y, az = p1.z - p0.z;
    float bx = p2.x - p0.x, by = p2.y - p0.y, bz = p2.z - p0.z;
    float nx = ay * bz - az * by;
    float ny = az * bx - ax * bz;
    float nz = ax * by - ay * bx;
    float nn = sqrtf(nx * nx + ny * ny + nz * nz);
    nx /= nn; ny /= nn; nz /= nn;
    float kk = -(nx * p1.x + ny * p1.y + nz * p1.z);
    g_plane[j] = make_float4(nx, ny, nz, kk);
}

// Stage C: inlier counts — EXACT measured-49us body (CT=512, 3 smem arrays,
// no min-blocks bound), fence/ticket tail removed (moved to k_best).
#define CT 512
#define CP (CT / 2)               // 256 pairs
#define CB (N_PTS / CT)           // 450, exact
__global__ void __launch_bounds__(256) k_counts(const int* __restrict__ ep) {
    __shared__ unsigned long long sx[CP], sy[CP], sz[CP];

    float th = get_thresh(*ep);
    float m = g_max;
    int t = threadIdx.x;

    // planes (broadcast into both packed halves)
    unsigned long long A[4], B4[4], C4[4], K4[4];
    int cnt[4] = {0, 0, 0, 0};
#pragma unroll
    for (int p = 0; p < 4; p++) {
        int j = t + p * 256;
        float4 pl = g_plane[j < N_PLANES ? j : 0];
        A[p]  = pack2(pl.x, pl.x);
        B4[p] = pack2(pl.y, pl.y);
        C4[p] = pack2(pl.z, pl.z);
        K4[p] = pack2(pl.w, pl.w);
    }

    // tile load: point pairs, normalized exactly like reference (f32 divide)
    int base = blockIdx.x * CT;
    {
        float4 q0 = g_pts[base + 2 * t];
        float4 q1 = g_pts[base + 2 * t + 1];
        sx[t] = pack2(q0.x / m, q1.x / m);
        sy[t] = pack2(q0.y / m, q1.y / m);
        sz[t] = pack2(q0.z / m, q1.z / m);
    }
    __syncthreads();

#pragma unroll 4
    for (int i = 0; i < CP; i++) {
        unsigned long long x2 = sx[i], y2 = sy[i], z2 = sz[i];
#pragma unroll
        for (int p = 0; p < 4; p++) {
            unsigned long long d2 = fma2(x2, A[p], fma2(y2, B4[p], fma2(z2, C4[p], K4[p])));
            float d0, d1; unpack2(d2, d0, d1);
            cnt[p] += (fabsf(d0) <= th);
            cnt[p] += (fabsf(d1) <= th);
        }
    }
#pragma unroll
    for (int p = 0; p < 4; p++) {
        int j = t + p * 256;
        if (j < N_PLANES) atomicAdd(&g_counts[j], cnt[p]);
    }
}

// Stage C2 (tiny): argmax (first max) + best-plane rotation + counts self-clean.
// 1024 threads, one plane each — no strided loop.
__global__ void k_best() {
    __shared__ int sv[1024], si[1024];
    int t = threadIdx.x;
    int val = -2;
    if (t < N_PLANES) {
        int cc = g_counts[t];
        val = (cc > MIN_PTS) ? cc : -1;
        g_counts[t] = 0;   // self-clean fused with read
    }
    sv[t] = val; si[t] = t;
    __syncthreads();
    for (int s = 512; s > 0; s >>= 1) {
        if (t < s) {
            if (sv[t + s] > sv[t] || (sv[t + s] == sv[t] && si[t + s] < si[t])) {
                sv[t] = sv[t + s]; si[t] = si[t + s];
            }
        }
        __syncthreads();
    }
    if (t == 0) {
        int best = si[0];
        float4 pl = g_plane[best];
        float a = pl.x, b = pl.y, c = pl.z, d = pl.w;
        float n2 = a * a + b * b + c * c;
        float cos_t = c / sqrtf(n2);
        float sin_t = sqrtf((a * a + b * b) / n2);
        float sab = sqrtf(a * a + b * b);
        float u1 = b / sab, u2 = -a / sab;
        g_bp[0] = a; g_bp[1] = b; g_bp[2] = c; g_bp[3] = d;
        g_bp[4] = -u2 * sin_t;   // R[2,0]
        g_bp[5] =  u1 * sin_t;   // R[2,1]
        g_bp[6] =  cos_t;        // R[2,2]
        g_bp[7] =  d / c;        // trans z
    }
}

// Stage D: single pass inlier stats, fence-free (tail in k_fin).
// Uses identity: sum|zc-zmax| = icnt*zmax - S, sum|zc-zmin| = S - icnt*zmin.
__global__ void k_zc(const int* __restrict__ ep) {
    float th = get_thresh(*ep);
    float m = g_max;
    int i = blockIdx.x * blockDim.x + threadIdx.x;
    float4 q = g_pts[i];
    float x = q.x / m, y = q.y / m, z = q.z / m;
    float dist = fmaf(x, g_bp[0], fmaf(y, g_bp[1], fmaf(z, g_bp[2], g_bp[3])));
    bool inl = fabsf(dist) <= th;
    float zc = x * g_bp[4] + y * g_bp[5] + (z + g_bp[7]) * g_bp[6];

    int    ic  = blockSumI(inl ? 1 : 0);
    float  zmx = blockMaxF(inl ? zc : -F_INF);
    float  zmn = blockMinF(inl ? zc :  F_INF);
    double s   = blockSumD(inl ? (double)zc : 0.0);
    if (threadIdx.x == 0) {
        atomicAdd(&g_icnt, ic);
        atomicMaxF(&g_zmax, zmx);
        atomicMinF(&g_zmin, zmn);
        atomicAdd(&g_sZC, s);
    }
}

// Stage E (tiny): finalize output + self-clean ALL accumulators.
__global__ void k_fin(float* __restrict__ out, int n) {
    if (threadIdx.x != 0) return;
    float cntf = (float)(g_cnt > 1 ? g_cnt : 1);
    float lX = sqrtf((float)g_sX / cntf);
    float lY = sqrtf((float)g_sY / cntf);
    float lZ = sqrtf((float)g_sZ / cntf);
    float rl = 10000.f * sqrtf((float)g_sL / cntf);
    float l17 = rl * fabsf(10.f * (3.f - expf(lX) - expf(lY) - expf(lZ)));

    int icr = g_icnt;
    float below, above;
    if (icr <= 0) {
        below = 0.f; above = 0.f;
    } else {
        float meanz = (float)(g_sZC / (double)icr);
        below = g_zmax - meanz;
        above = meanz - g_zmin;
    }
    if (above == 0.f) above = 1e-7f;
    float pmd = 1000.f * (above + below);
    float curv = l17 + pmd;
    float vals[7] = { rl, lX, lY, lZ, pmd, l17, curv };
    for (int k = 0; k < n; k++) out[k] = (k < 7) ? vals[k] : 0.f;

    // self-clean for next call
    g_sX = 0.0; g_sY = 0.0; g_sZ = 0.0; g_sL = 0.0;
    g_cnt = 0;  g_icnt = 0;
    g_max  = NEG_FLT_MAX;
    g_zmax = NEG_FLT_MAX;
    g_zmin = POS_FLT_MAX;
    g_sZC  = 0.0;
}

// ---------------- launch ----------------
extern "C" void kernel_launch(void* const* d_in, const int* in_sizes, int n_in,
                              void* d_out, int out_size) {
    const float* fake = (const float*)d_in[0];
    const float* real = (const float*)d_in[1];
    const int*   ep   = (const int*)d_in[2];
    float* out = (float*)d_out;

    const int NB = N_PTS / 256;  // 900, exact

    k_pcd<<<NB, 256>>>(fake, real);
    k_planes<<<8, 128>>>();
    k_counts<<<CB, 256>>>(ep);
    k_best<<<1, 1024>>>();
    k_zc<<<NB, 256>>>(ep);
    k_fin<<<1, 32>>>(out, out_size);
}